// round 9
// baseline (speedup 1.0000x reference)
#include <cuda_runtime.h>
#include <cstdint>

#define IN_F    4096
#define OUT_F   11008
#define MROWS   128
#define NTILE   64
#define KCH     64              // K elements per stage
#define KITERS  (IN_F / KCH)    // 64
#define NCTAS   (OUT_F / NTILE) // 172
#define RSTR    80              // padded int8 smem row stride (64 + 16)
#define A_ROWS  256
#define W8OFF   (A_ROWS * RSTR)          // 20480
#define W32STR  272                      // 64*4 + 16 pad
#define W32OFF  (W8OFF + NTILE * RSTR)   // 25600
#define STAGE_B (W32OFF + NTILE * W32STR) // 43008
#define NSTAGE  4
#define SMEM_DYN (NSTAGE * STAGE_B)      // 172032

__device__ __align__(256) int8_t g_q[256 * IN_F];  // rows 0-127: q1, 128-255: q2
__device__ float g_s1[MROWS];

// ------------------------------------------------ kernel 1: quantize x -----
__global__ void kq_quant(const float* __restrict__ x) {
    int m = blockIdx.x, t = threadIdx.x;
    const float4* xr = reinterpret_cast<const float4*>(x + (size_t)m * IN_F);
    float4 v[4];
#pragma unroll
    for (int i = 0; i < 4; ++i) v[i] = xr[t * 4 + i];
    float amax = 0.f;
#pragma unroll
    for (int i = 0; i < 4; ++i)
        amax = fmaxf(amax, fmaxf(fmaxf(fabsf(v[i].x), fabsf(v[i].y)),
                                 fmaxf(fabsf(v[i].z), fabsf(v[i].w))));
#pragma unroll
    for (int o = 16; o > 0; o >>= 1) amax = fmaxf(amax, __shfl_xor_sync(0xFFFFFFFFu, amax, o));
    __shared__ float red[8];
    if ((t & 31) == 0) red[t >> 5] = amax;
    __syncthreads();
    float am = red[0];
#pragma unroll
    for (int i = 1; i < 8; ++i) am = fmaxf(am, red[i]);
    am = fmaxf(am, 1e-20f);
    float s1 = am * (1.0f / 127.0f);
    float inv1 = 127.0f / am;
    float inv2 = inv1 * 127.0f;
    int8_t q1[16], q2[16];
#pragma unroll
    for (int i = 0; i < 4; ++i) {
        float xs[4] = {v[i].x, v[i].y, v[i].z, v[i].w};
#pragma unroll
        for (int e = 0; e < 4; ++e) {
            float a = rintf(xs[e] * inv1);
            float r = fmaf(-a, s1, xs[e]);
            q1[i * 4 + e] = (int8_t)(int)a;
            q2[i * 4 + e] = (int8_t)(int)rintf(r * inv2);
        }
    }
    *reinterpret_cast<int4*>(g_q + (size_t)m * IN_F + t * 16) = *reinterpret_cast<int4*>(q1);
    *reinterpret_cast<int4*>(g_q + (size_t)(128 + m) * IN_F + t * 16) = *reinterpret_cast<int4*>(q2);
    if (t == 0) g_s1[m] = s1;
}

// ------------------------------------------------ kernel 2: i8 GEMM --------
__device__ __forceinline__ void kq_mma(int* c, const uint32_t* a, const uint32_t* b) {
    asm volatile(
        "mma.sync.aligned.m16n8k32.row.col.s32.s8.s8.s32 "
        "{%0,%1,%2,%3}, {%4,%5,%6,%7}, {%8,%9}, {%0,%1,%2,%3};"
        : "+r"(c[0]), "+r"(c[1]), "+r"(c[2]), "+r"(c[3])
        : "r"(a[0]), "r"(a[1]), "r"(a[2]), "r"(a[3]), "r"(b[0]), "r"(b[1]));
}
__device__ __forceinline__ void kq_ldsm4(uint32_t* r, uint32_t addr) {
    asm volatile("ldmatrix.sync.aligned.m8n8.x4.shared.b16 {%0,%1,%2,%3}, [%4];"
                 : "=r"(r[0]), "=r"(r[1]), "=r"(r[2]), "=r"(r[3]) : "r"(addr));
}
__device__ __forceinline__ void kq_ldsm2(uint32_t* r, uint32_t addr) {
    asm volatile("ldmatrix.sync.aligned.m8n8.x2.shared.b16 {%0,%1}, [%2];"
                 : "=r"(r[0]), "=r"(r[1]) : "r"(addr));
}

// stage load: q (int8 from g_q) + W (int32 raw)
__device__ __forceinline__ void kq_load_stage(char* sm, int slot, int j, int t,
                                              const int* __restrict__ W, int n0) {
    char* sb = sm + (size_t)slot * STAGE_B;
    // q tile: 256 rows x 64B = 1024 x 16B chunks, 4 per thread
#pragma unroll
    for (int i = 0; i < 4; ++i) {
        int c = t + (i << 8);
        int row = c >> 2, off = (c & 3) << 4;
        uint32_t dst;
        asm("{ .reg .u64 u; cvta.to.shared.u64 u, %1; cvt.u32.u64 %0, u; }"
            : "=r"(dst) : "l"(sb + row * RSTR + off));
        const int8_t* src = g_q + (size_t)row * IN_F + j * KCH + off;
        asm volatile("cp.async.cg.shared.global [%0], [%1], 16;" :: "r"(dst), "l"(src) : "memory");
    }
    // W32 tile: 64 rows x 256B = 1024 x 16B chunks, 4 per thread
#pragma unroll
    for (int i = 0; i < 4; ++i) {
        int c = t + (i << 8);
        int row = c >> 4, ch = c & 15;          // ch = 16B chunk within row
        uint32_t dst;
        asm("{ .reg .u64 u; cvta.to.shared.u64 u, %1; cvt.u32.u64 %0, u; }"
            : "=r"(dst) : "l"(sb + W32OFF + row * W32STR + ch * 16));
        const int* src = W + (size_t)(n0 + row) * IN_F + j * KCH + ch * 4;
        asm volatile("cp.async.cg.shared.global [%0], [%1], 16;" :: "r"(dst), "l"(src) : "memory");
    }
}

// pack W32 stage -> W8 region (each thread: 16 int32 -> 16 int8)
__device__ __forceinline__ void kq_pack_w(char* sm, int slot, int t) {
    char* sb = sm + (size_t)slot * STAGE_B;
    int row = t >> 2, cb = (t & 3) * 16;        // 16-element chunk base
    const char* src = sb + W32OFF + row * W32STR + cb * 4;
    uint32_t o[4];
#pragma unroll
    for (int c4 = 0; c4 < 4; ++c4) {
        int4 v = *reinterpret_cast<const int4*>(src + c4 * 16);
        o[c4] = (v.x & 0xFF) | ((v.y & 0xFF) << 8) | ((v.z & 0xFF) << 16) | ((uint32_t)v.w << 24);
    }
    int4 w;
    w.x = o[0]; w.y = o[1]; w.z = o[2]; w.w = o[3];
    *reinterpret_cast<int4*>(sb + W8OFF + row * RSTR + cb) = w;
}

__global__ void __launch_bounds__(256, 1)
kq_gemm(const int* __restrict__ W, const float* __restrict__ scale,
        const float* __restrict__ bias, float* __restrict__ out) {
    extern __shared__ char sm[];
    const int t = threadIdx.x;
    const int lane = t & 31, warp = t >> 5;
    const int wm = warp >> 1, wn = warp & 1;      // 4 (M) x 2 (N) warp grid
    const int g = lane >> 2, q = lane & 3;
    const int n0 = blockIdx.x * NTILE;

    uint32_t smb;
    asm("{ .reg .u64 u; cvta.to.shared.u64 u, %1; cvt.u32.u64 %0, u; }" : "=r"(smb) : "l"(sm));

    int acc1[2][4][4] = {}, acc2[2][4][4] = {};

    // prologue: stages 0..2
#pragma unroll
    for (int j = 0; j < NSTAGE - 1; ++j) {
        kq_load_stage(sm, j, j, t, W, n0);
        asm volatile("cp.async.commit_group;" ::: "memory");
    }

    const int lrowA = lane & 15;
    const int lkA   = (lane >> 4) << 4;
    const int lrowB = lane & 7;
    const int lkB   = ((lane >> 3) & 1) << 4;
    const int arow1 = wm * 32;
    const int arow2 = 128 + wm * 32;

#pragma unroll 1
    for (int ki = 0; ki < KITERS; ++ki) {
        asm volatile("cp.async.wait_group %0;" :: "n"(NSTAGE - 2) : "memory");
        __syncthreads();                             // stage ki (q + w32) resident
        int jl = ki + NSTAGE - 1;
        if (jl < KITERS) kq_load_stage(sm, jl & (NSTAGE - 1), jl, t, W, n0);
        asm volatile("cp.async.commit_group;" ::: "memory");

        kq_pack_w(sm, ki & (NSTAGE - 1), t);         // w32 -> w8
        __syncthreads();                             // w8 visible to ldmatrix

        uint32_t st = smb + (uint32_t)(ki & (NSTAGE - 1)) * STAGE_B;
#pragma unroll
        for (int ks = 0; ks < 2; ++ks) {
            const int kof = ks * 32;
            uint32_t b[4][2];
#pragma unroll
            for (int nf = 0; nf < 4; ++nf)
                kq_ldsm2(b[nf], st + W8OFF + (uint32_t)((wn * 32 + nf * 8 + lrowB) * RSTR + kof + lkB));
#pragma unroll
            for (int mf = 0; mf < 2; ++mf) {
                uint32_t a1[4], a2[4];
                kq_ldsm4(a1, st + (uint32_t)((arow1 + mf * 16 + lrowA) * RSTR + kof + lkA));
                kq_ldsm4(a2, st + (uint32_t)((arow2 + mf * 16 + lrowA) * RSTR + kof + lkA));
#pragma unroll
                for (int nf = 0; nf < 4; ++nf) {
                    kq_mma(acc1[mf][nf], a1, b[nf]);
                    kq_mma(acc2[mf][nf], a2, b[nf]);
                }
            }
        }
    }

    // ---------------- epilogue: warp-local two-level combine, direct gmem --
    const float sc = scale[0];
#pragma unroll
    for (int mf = 0; mf < 2; ++mf) {
        int r0 = wm * 32 + mf * 16 + g;
        int r1 = r0 + 8;
        float s1a = g_s1[r0], s1b = g_s1[r1];
        float s2a = s1a * (1.0f / 127.0f), s2b = s1b * (1.0f / 127.0f);
#pragma unroll
        for (int nf = 0; nf < 4; ++nf) {
            int c = n0 + wn * 32 + nf * 8 + 2 * q;
            float b0 = bias[c], b1 = bias[c + 1];
            float2 v0, v1;
            v0.x = fmaf(sc, fmaf(s1a, (float)acc1[mf][nf][0], s2a * (float)acc2[mf][nf][0]), b0);
            v0.y = fmaf(sc, fmaf(s1a, (float)acc1[mf][nf][1], s2a * (float)acc2[mf][nf][1]), b1);
            v1.x = fmaf(sc, fmaf(s1b, (float)acc1[mf][nf][2], s2b * (float)acc2[mf][nf][2]), b0);
            v1.y = fmaf(sc, fmaf(s1b, (float)acc1[mf][nf][3], s2b * (float)acc2[mf][nf][3]), b1);
            *reinterpret_cast<float2*>(out + (size_t)r0 * OUT_F + c) = v0;
            *reinterpret_cast<float2*>(out + (size_t)r1 * OUT_F + c) = v1;
        }
    }
}

// ------------------------------------------------------------- launcher ----
extern "C" void kernel_launch(void* const* d_in, const int* in_sizes, int n_in,
                              void* d_out, int out_size) {
    const float* x     = (const float*)d_in[0];
    const int*   w     = (const int*)d_in[1];      // int8 weights delivered as int32
    const float* scale = (const float*)d_in[2];
    const float* bias  = (const float*)d_in[3];
    float*       out   = (float*)d_out;
    cudaFuncSetAttribute(kq_gemm, cudaFuncAttributeMaxDynamicSharedMemorySize, SMEM_DYN);
    kq_quant<<<MROWS, 256>>>(x);
    kq_gemm<<<NCTAS, 256, SMEM_DYN>>>(w, scale, bias, out);
}

// round 13
// speedup vs baseline: 1.4568x; 1.4568x over previous
#include <cuda_runtime.h>
#include <cstdint>

#define IN_F    4096
#define OUT_F   11008
#define MROWS   128
#define NTILE   64
#define KCH     64                 // K elements per stage
#define HK      32                 // k-iters per K-half (K-split 2)
#define NCTAS   (2 * OUT_F / NTILE)  // 344
#define RSTR    80                 // padded int8 smem row stride
#define A_ROWS  256
#define QSTAGE_B (A_ROWS * RSTR)   // 20480
#define NQSTAGE 4
#define W8OFF   (NQSTAGE * QSTAGE_B)      // 81920
#define W8_B    (NTILE * RSTR)            // 5120
#define SMEM_DYN (W8OFF + 2 * W8_B)       // 92160

__device__ __align__(256) int8_t g_q[256 * IN_F];   // rows 0-127: q1, 128-255: q2
__device__ float g_s1[MROWS];
__device__ float g_part[2 * MROWS * OUT_F];         // K-split partials (11.3 MB)

// ------------------------------------------------ kernel 1: quantize x -----
__global__ void kq_quant(const float* __restrict__ x) {
    int m = blockIdx.x, t = threadIdx.x;
    const float4* xr = reinterpret_cast<const float4*>(x + (size_t)m * IN_F);
    float4 v[4];
#pragma unroll
    for (int i = 0; i < 4; ++i) v[i] = xr[t * 4 + i];
    float amax = 0.f;
#pragma unroll
    for (int i = 0; i < 4; ++i)
        amax = fmaxf(amax, fmaxf(fmaxf(fabsf(v[i].x), fabsf(v[i].y)),
                                 fmaxf(fabsf(v[i].z), fabsf(v[i].w))));
#pragma unroll
    for (int o = 16; o > 0; o >>= 1) amax = fmaxf(amax, __shfl_xor_sync(0xFFFFFFFFu, amax, o));
    __shared__ float red[8];
    if ((t & 31) == 0) red[t >> 5] = amax;
    __syncthreads();
    float am = red[0];
#pragma unroll
    for (int i = 1; i < 8; ++i) am = fmaxf(am, red[i]);
    am = fmaxf(am, 1e-20f);
    float s1 = am * (1.0f / 127.0f);
    float inv1 = 127.0f / am;
    float inv2 = inv1 * 127.0f;
    int8_t q1[16], q2[16];
#pragma unroll
    for (int i = 0; i < 4; ++i) {
        float xs[4] = {v[i].x, v[i].y, v[i].z, v[i].w};
#pragma unroll
        for (int e = 0; e < 4; ++e) {
            float a = rintf(xs[e] * inv1);
            float r = fmaf(-a, s1, xs[e]);
            q1[i * 4 + e] = (int8_t)(int)a;
            q2[i * 4 + e] = (int8_t)(int)rintf(r * inv2);
        }
    }
    *reinterpret_cast<int4*>(g_q + (size_t)m * IN_F + t * 16) = *reinterpret_cast<int4*>(q1);
    *reinterpret_cast<int4*>(g_q + (size_t)(128 + m) * IN_F + t * 16) = *reinterpret_cast<int4*>(q2);
    if (t == 0) g_s1[m] = s1;
}

// ------------------------------------------------ kernel 2: i8 GEMM --------
__device__ __forceinline__ void kq_mma(int* c, const uint32_t* a, const uint32_t* b) {
    asm volatile(
        "mma.sync.aligned.m16n8k32.row.col.s32.s8.s8.s32 "
        "{%0,%1,%2,%3}, {%4,%5,%6,%7}, {%8,%9}, {%0,%1,%2,%3};"
        : "+r"(c[0]), "+r"(c[1]), "+r"(c[2]), "+r"(c[3])
        : "r"(a[0]), "r"(a[1]), "r"(a[2]), "r"(a[3]), "r"(b[0]), "r"(b[1]));
}
__device__ __forceinline__ void kq_ldsm4(uint32_t* r, uint32_t addr) {
    asm volatile("ldmatrix.sync.aligned.m8n8.x4.shared.b16 {%0,%1,%2,%3}, [%4];"
                 : "=r"(r[0]), "=r"(r[1]), "=r"(r[2]), "=r"(r[3]) : "r"(addr));
}
__device__ __forceinline__ void kq_ldsm2(uint32_t* r, uint32_t addr) {
    asm volatile("ldmatrix.sync.aligned.m8n8.x2.shared.b16 {%0,%1}, [%2];"
                 : "=r"(r[0]), "=r"(r[1]) : "r"(addr));
}

// q stage load: 256 rows x 64B via cp.async
__device__ __forceinline__ void kq_load_q(char* sm, int slot, int jg, int t) {
    char* sb = sm + (size_t)slot * QSTAGE_B;
#pragma unroll
    for (int i = 0; i < 4; ++i) {
        int c = t + (i << 8);
        int row = c >> 2, off = (c & 3) << 4;
        uint32_t dst;
        asm("{ .reg .u64 u; cvta.to.shared.u64 u, %1; cvt.u32.u64 %0, u; }"
            : "=r"(dst) : "l"(sb + row * RSTR + off));
        const int8_t* src = g_q + (size_t)row * IN_F + jg * KCH + off;
        asm volatile("cp.async.cg.shared.global [%0], [%1], 16;" :: "r"(dst), "l"(src) : "memory");
    }
}
// W prefetch: 16 int32 per thread (row = t>>2, 16-elem chunk = t&3)
__device__ __forceinline__ void kq_ldg_w(int4* wr, const int* __restrict__ W,
                                         int n0, int jg, int t) {
    const int4* src = reinterpret_cast<const int4*>(
        W + (size_t)(n0 + (t >> 2)) * IN_F + jg * KCH + (t & 3) * 16);
#pragma unroll
    for (int i = 0; i < 4; ++i) wr[i] = src[i];
}
// pack 16 int32 -> 16 int8, STS into w8 buffer
__device__ __forceinline__ void kq_pack_sts(char* sm, int buf, const int4* wr, int t) {
    uint32_t o[4];
#pragma unroll
    for (int i = 0; i < 4; ++i) {
        o[i] = (wr[i].x & 0xFF) | ((wr[i].y & 0xFF) << 8) |
               ((wr[i].z & 0xFF) << 16) | ((uint32_t)wr[i].w << 24);
    }
    int4 v; v.x = o[0]; v.y = o[1]; v.z = o[2]; v.w = o[3];
    *reinterpret_cast<int4*>(sm + W8OFF + (size_t)buf * W8_B + (t >> 2) * RSTR + (t & 3) * 16) = v;
}

__global__ void __launch_bounds__(256, 2)
kq_gemm(const int* __restrict__ W, const float* __restrict__ scale) {
    extern __shared__ char sm[];
    const int t = threadIdx.x;
    const int lane = t & 31, warp = t >> 5;
    const int wm = warp >> 1, wn = warp & 1;      // 4 (M) x 2 (N) warp grid
    const int g = lane >> 2, q = lane & 3;
    const int h  = blockIdx.x & 1;                // K-half
    const int n0 = (blockIdx.x >> 1) * NTILE;
    const int kb = h * HK;                        // k-iter base

    uint32_t smb;
    asm("{ .reg .u64 u; cvta.to.shared.u64 u, %1; cvt.u32.u64 %0, u; }" : "=r"(smb) : "l"(sm));

    int acc1[2][4][4] = {}, acc2[2][4][4] = {};
    int4 wr[4];

    // prologue: q stages 0..2, W for ki=0 packed, W for ki=1 in regs
#pragma unroll
    for (int j = 0; j < NQSTAGE - 1; ++j) {
        kq_load_q(sm, j, kb + j, t);
        asm volatile("cp.async.commit_group;" ::: "memory");
    }
    kq_ldg_w(wr, W, n0, kb + 0, t);
    kq_pack_sts(sm, 0, wr, t);
    kq_ldg_w(wr, W, n0, kb + 1, t);
    asm volatile("cp.async.wait_group %0;" :: "n"(NQSTAGE - 2) : "memory");
    __syncthreads();

    const int lrowA = lane & 15;
    const int lkA   = (lane >> 4) << 4;
    const int lrowB = lane & 7;
    const int lkB   = ((lane >> 3) & 1) << 4;
    const int arow1 = wm * 32;
    const int arow2 = 128 + wm * 32;

#pragma unroll 1
    for (int ki = 0; ki < HK; ++ki) {
        // 1. pack W(ki+1) from regs into the other w8 buffer
        if (ki + 1 < HK) kq_pack_sts(sm, (ki + 1) & 1, wr, t);
        // 2. prefetch W(ki+2) (latency hidden under mma block)
        if (ki + 2 < HK) kq_ldg_w(wr, W, n0, kb + ki + 2, t);

        // 3. mma block on q stage ki, w8 buffer ki&1
        uint32_t stq = smb + (uint32_t)(ki & (NQSTAGE - 1)) * QSTAGE_B;
        uint32_t stw = smb + W8OFF + (uint32_t)(ki & 1) * W8_B;
#pragma unroll
        for (int ks = 0; ks < 2; ++ks) {
            const int kof = ks * 32;
            uint32_t b[4][2];
#pragma unroll
            for (int nf = 0; nf < 4; ++nf)
                kq_ldsm2(b[nf], stw + (uint32_t)((wn * 32 + nf * 8 + lrowB) * RSTR + kof + lkB));
#pragma unroll
            for (int mf = 0; mf < 2; ++mf) {
                uint32_t a1[4], a2[4];
                kq_ldsm4(a1, stq + (uint32_t)((arow1 + mf * 16 + lrowA) * RSTR + kof + lkA));
                kq_ldsm4(a2, stq + (uint32_t)((arow2 + mf * 16 + lrowA) * RSTR + kof + lkA));
#pragma unroll
                for (int nf = 0; nf < 4; ++nf) {
                    kq_mma(acc1[mf][nf], a1, b[nf]);
                    kq_mma(acc2[mf][nf], a2, b[nf]);
                }
            }
        }

        // 4. next q stage
        if (ki + NQSTAGE - 1 < HK) kq_load_q(sm, (ki + 3) & (NQSTAGE - 1), kb + ki + 3, t);
        asm volatile("cp.async.commit_group;" ::: "memory");
        asm volatile("cp.async.wait_group %0;" :: "n"(NQSTAGE - 2) : "memory");
        __syncthreads();   // covers: w8 STS visibility, q stage readiness & reuse
    }

    // ---------------- epilogue: partials (scale applied, no bias) ----------
    const float sc = scale[0];
    float* part = g_part + (size_t)h * MROWS * OUT_F;
#pragma unroll
    for (int mf = 0; mf < 2; ++mf) {
        int r0 = wm * 32 + mf * 16 + g;
        int r1 = r0 + 8;
        float s1a = g_s1[r0], s1b = g_s1[r1];
        float s2a = s1a * (1.0f / 127.0f), s2b = s1b * (1.0f / 127.0f);
#pragma unroll
        for (int nf = 0; nf < 4; ++nf) {
            int c = n0 + wn * 32 + nf * 8 + 2 * q;
            float2 v0, v1;
            v0.x = sc * fmaf(s1a, (float)acc1[mf][nf][0], s2a * (float)acc2[mf][nf][0]);
            v0.y = sc * fmaf(s1a, (float)acc1[mf][nf][1], s2a * (float)acc2[mf][nf][1]);
            v1.x = sc * fmaf(s1b, (float)acc1[mf][nf][2], s2b * (float)acc2[mf][nf][2]);
            v1.y = sc * fmaf(s1b, (float)acc1[mf][nf][3], s2b * (float)acc2[mf][nf][3]);
            *reinterpret_cast<float2*>(part + (size_t)r0 * OUT_F + c) = v0;
            *reinterpret_cast<float2*>(part + (size_t)r1 * OUT_F + c) = v1;
        }
    }
}

// ------------------------------------------------ kernel 3: reduce ---------
__global__ void kq_reduce(const float* __restrict__ bias, float* __restrict__ out) {
    size_t i = ((size_t)blockIdx.x * 256 + threadIdx.x) * 4;
    if (i >= (size_t)MROWS * OUT_F) return;
    float4 p0 = *reinterpret_cast<const float4*>(g_part + i);
    float4 p1 = *reinterpret_cast<const float4*>(g_part + (size_t)MROWS * OUT_F + i);
    int n = (int)(i % OUT_F);
    float4 b = *reinterpret_cast<const float4*>(bias + n);
    float4 o;
    o.x = p0.x + p1.x + b.x;
    o.y = p0.y + p1.y + b.y;
    o.z = p0.z + p1.z + b.z;
    o.w = p0.w + p1.w + b.w;
    *reinterpret_cast<float4*>(out + i) = o;
}

// ------------------------------------------------------------- launcher ----
extern "C" void kernel_launch(void* const* d_in, const int* in_sizes, int n_in,
                              void* d_out, int out_size) {
    const float* x     = (const float*)d_in[0];
    const int*   w     = (const int*)d_in[1];      // int8 weights delivered as int32
    const float* scale = (const float*)d_in[2];
    const float* bias  = (const float*)d_in[3];
    float*       out   = (float*)d_out;
    cudaFuncSetAttribute(kq_gemm, cudaFuncAttributeMaxDynamicSharedMemorySize, SMEM_DYN);
    kq_quant<<<MROWS, 256>>>(x);
    kq_gemm<<<NCTAS, 256, SMEM_DYN>>>(w, scale);
    int total4 = (MROWS * OUT_F) / 4;              // 352256
    kq_reduce<<<(total4 + 255) / 256, 256>>>(bias, out);
}